// round 1
// baseline (speedup 1.0000x reference)
#include <cuda_runtime.h>
#include <math.h>

// Problem constants (fixed by the reference)
#define Bn    8
#define Tn    128
#define Un    64
#define U1    65        // U + 1
#define Vn    1024
#define BLANKC 1023     // blank = V-1
#define NEGF  (-1e30f)

// Scratch: per-row log-probs needed by the DP.
// lp_blank: (B, T, U+1), lp_emit: (B, T, U)
__device__ float g_lp_blank[Bn * Tn * U1];
__device__ float g_lp_emit[Bn * Tn * Un];

// ---------------------------------------------------------------------------
// Kernel A: one warp per (b,t,u) row of V=1024 logits.
// Computes lse = logsumexp(row), then writes
//   lp_blank[row] = logits[row, BLANK] - lse
//   lp_emit[b,t,u] = logits[row, targets[b,u]] - lse   (u < U)
// ---------------------------------------------------------------------------
__global__ void __launch_bounds__(256)
lse_gather_kernel(const float* __restrict__ logits,
                  const int* __restrict__ targets)
{
    const int warp_id = (blockIdx.x * blockDim.x + threadIdx.x) >> 5;
    const int lane    = threadIdx.x & 31;
    const int nrows   = Bn * Tn * U1;
    if (warp_id >= nrows) return;

    const float4* row4 = reinterpret_cast<const float4*>(
        logits + (size_t)warp_id * Vn);

    // Each lane loads 8 float4 = 32 floats (coalesced: lane + 32*i)
    float4 v[8];
#pragma unroll
    for (int i = 0; i < 8; i++) v[i] = row4[lane + 32 * i];

    // max
    float m = -INFINITY;
#pragma unroll
    for (int i = 0; i < 8; i++) {
        m = fmaxf(m, fmaxf(fmaxf(v[i].x, v[i].y), fmaxf(v[i].z, v[i].w)));
    }
#pragma unroll
    for (int o = 16; o > 0; o >>= 1)
        m = fmaxf(m, __shfl_xor_sync(0xffffffffu, m, o));

    // sum of exp(x - m)
    float s = 0.f;
#pragma unroll
    for (int i = 0; i < 8; i++) {
        s += __expf(v[i].x - m) + __expf(v[i].y - m)
           + __expf(v[i].z - m) + __expf(v[i].w - m);
    }
#pragma unroll
    for (int o = 16; o > 0; o >>= 1)
        s += __shfl_xor_sync(0xffffffffu, s, o);

    if (lane == 0) {
        const float lse = m + logf(s);
        const int b   = warp_id / (Tn * U1);
        const int rem = warp_id % (Tn * U1);
        const int t   = rem / U1;
        const int u   = rem % U1;
        const float* rowf = logits + (size_t)warp_id * Vn;
        // Row was just streamed through L1 -> these re-loads are cache hits.
        g_lp_blank[warp_id] = rowf[BLANKC] - lse;
        if (u < Un) {
            const int tgt = targets[b * Un + u];
            g_lp_emit[(b * Tn + t) * Un + u] = rowf[tgt] - lse;
        }
    }
}

// ---------------------------------------------------------------------------
// Kernel B: anti-diagonal wavefront DP. One block per batch, thread u owns
// column u of alpha. alpha[t][u] = logaddexp(alpha[t-1][u] + blank[t-1][u],
//                                            alpha[t][u-1] + emit[t][u-1])
// Cells on diagonal d = t+u depend only on diagonal d-1.
// ---------------------------------------------------------------------------
__global__ void __launch_bounds__(U1)
rnnt_dp_kernel(const int* __restrict__ logit_lengths,
               const int* __restrict__ target_lengths,
               float* __restrict__ out)
{
    const int b = blockIdx.x;
    const int u = threadIdx.x;        // 0..64

    __shared__ float sh[2][U1];

    const int t_last = logit_lengths[b] - 1;
    const int u_last = target_lengths[b];

    const float* lpb = g_lp_blank + b * Tn * U1;
    const float* lpe = g_lp_emit  + b * Tn * Un;

    float myPrev = NEGF;              // alpha[t-1][u] (this thread, prev diag)
    sh[1][u] = NEGF;                  // "previous" buffer for d=0
    __syncthreads();

    for (int d = 0; d < Tn + Un; d++) {
        const int pb = (d + 1) & 1;   // prev-diagonal buffer
        const int cb = d & 1;         // current buffer
        float val = NEGF;
        const int t = d - u;
        if (t >= 0 && t < Tn) {
            if (d == 0) {
                val = 0.f;            // alpha[0][0]
            } else {
                const float up   = (t > 0)
                    ? myPrev + lpb[(t - 1) * U1 + u] : NEGF;
                const float left = (u > 0)
                    ? sh[pb][u - 1] + lpe[t * Un + (u - 1)] : NEGF;
                const float mx = fmaxf(up, left);
                const float mn = fminf(up, left);
                val = mx + log1pf(__expf(mn - mx));
            }
            if (t == t_last && u == u_last) {
                out[b] = -(val + lpb[t * U1 + u]);
            }
        }
        sh[cb][u] = val;
        myPrev = val;
        __syncthreads();
    }
}

// ---------------------------------------------------------------------------
// Launch
// Inputs (metadata order): logits f32, targets i32, logit_lengths i32,
//                          target_lengths i32. Output: f32[B].
// ---------------------------------------------------------------------------
extern "C" void kernel_launch(void* const* d_in, const int* in_sizes, int n_in,
                              void* d_out, int out_size)
{
    const float* logits         = (const float*)d_in[0];
    const int*   targets        = (const int*)d_in[1];
    const int*   logit_lengths  = (const int*)d_in[2];
    const int*   target_lengths = (const int*)d_in[3];
    float*       out            = (float*)d_out;

    const int nrows   = Bn * Tn * U1;          // 66560 rows, one warp each
    const int threads = 256;                   // 8 warps / block
    const int blocks  = (nrows * 32 + threads - 1) / threads;

    lse_gather_kernel<<<blocks, threads>>>(logits, targets);
    rnnt_dp_kernel<<<Bn, U1>>>(logit_lengths, target_lengths, out);
}

// round 3
// speedup vs baseline: 1.7504x; 1.7504x over previous
#include <cuda_runtime.h>
#include <math.h>

// Problem constants (fixed by the reference)
#define Bn    8
#define Tn    128
#define Un    64
#define U1    65        // U + 1
#define Vn    1024
#define BLANKC 1023     // blank = V-1
#define NEGF  (-1e30f)
#define SPAD  66        // padded row stride for shared tiles (conflict-free)

// Scratch: per-row log-probs needed by the DP.
// lp_blank: (B, T, U+1), lp_emit: (B, T, U)
__device__ float g_lp_blank[Bn * Tn * U1];
__device__ float g_lp_emit[Bn * Tn * Un];

// ---------------------------------------------------------------------------
// Kernel A: one warp per (b,t,u) row of V=1024 logits.  (at HBM roofline)
// ---------------------------------------------------------------------------
__global__ void __launch_bounds__(256)
lse_gather_kernel(const float* __restrict__ logits,
                  const int* __restrict__ targets)
{
    const int warp_id = (blockIdx.x * blockDim.x + threadIdx.x) >> 5;
    const int lane    = threadIdx.x & 31;
    const int nrows   = Bn * Tn * U1;
    if (warp_id >= nrows) return;

    const float4* row4 = reinterpret_cast<const float4*>(
        logits + (size_t)warp_id * Vn);

    float4 v[8];
#pragma unroll
    for (int i = 0; i < 8; i++) v[i] = row4[lane + 32 * i];

    float m = -INFINITY;
#pragma unroll
    for (int i = 0; i < 8; i++) {
        m = fmaxf(m, fmaxf(fmaxf(v[i].x, v[i].y), fmaxf(v[i].z, v[i].w)));
    }
#pragma unroll
    for (int o = 16; o > 0; o >>= 1)
        m = fmaxf(m, __shfl_xor_sync(0xffffffffu, m, o));

    float s = 0.f;
#pragma unroll
    for (int i = 0; i < 8; i++) {
        s += __expf(v[i].x - m) + __expf(v[i].y - m)
           + __expf(v[i].z - m) + __expf(v[i].w - m);
    }
#pragma unroll
    for (int o = 16; o > 0; o >>= 1)
        s += __shfl_xor_sync(0xffffffffu, s, o);

    if (lane == 0) {
        const float lse = m + logf(s);
        const int b   = warp_id / (Tn * U1);
        const int rem = warp_id % (Tn * U1);
        const int t   = rem / U1;
        const int u   = rem % U1;
        const float* rowf = logits + (size_t)warp_id * Vn;
        g_lp_blank[warp_id] = rowf[BLANKC] - lse;
        if (u < Un) {
            const int tgt = targets[b * Un + u];
            g_lp_emit[(b * Tn + t) * Un + u] = rowf[tgt] - lse;
        }
    }
}

// ---------------------------------------------------------------------------
// Kernel B: anti-diagonal wavefront DP, now fully shared-memory resident.
// One block (128 threads) per batch. All 128 threads preload lp_blank/lp_emit
// into padded shared tiles; threads 0..64 run the wavefront.
//
// Shared tiles padded to row stride 66 so the diagonal access pattern
// addr = (d-u-1)*66 + u  has u-stride -65 == -1 (mod 32)  -> conflict-free.
// ---------------------------------------------------------------------------
__global__ void __launch_bounds__(128)
rnnt_dp_kernel(const int* __restrict__ logit_lengths,
               const int* __restrict__ target_lengths,
               float* __restrict__ out)
{
    const int b   = blockIdx.x;
    const int tid = threadIdx.x;
    const int u   = tid;              // valid DP thread iff u < U1

    __shared__ float s_lpb[Tn * SPAD];   // (t, u) blank log-probs
    __shared__ float s_lpe[Tn * SPAD];   // (t, u) emit  log-probs
    __shared__ float sh[2][U1];          // diagonal exchange buffers

    // ---- preload (coalesced global reads, swizzled shared writes) ----
    {
        const float* lpb_g = g_lp_blank + b * Tn * U1;
        const float* lpe_g = g_lp_emit  + b * Tn * Un;
        for (int i = tid; i < Tn * U1; i += 128) {
            const int t = i / U1, c = i - t * U1;
            s_lpb[t * SPAD + c] = lpb_g[i];
        }
        for (int i = tid; i < Tn * Un; i += 128) {
            const int t = i / Un, c = i - t * Un;
            s_lpe[t * SPAD + c] = lpe_g[i];
        }
    }

    const int t_last = logit_lengths[b] - 1;
    const int u_last = target_lengths[b];

    float myPrev = NEGF;
    if (u < U1) sh[1][u] = NEGF;
    __syncthreads();

    for (int d = 0; d < Tn + Un; d++) {
        const int pb = (d + 1) & 1;
        const int cb = d & 1;
        if (u < U1) {
            float val = NEGF;
            const int t = d - u;
            if (t >= 0 && t < Tn) {
                if (d == 0) {
                    val = 0.f;
                } else {
                    const float up   = (t > 0)
                        ? myPrev + s_lpb[(t - 1) * SPAD + u] : NEGF;
                    const float left = (u > 0)
                        ? sh[pb][u - 1] + s_lpe[t * SPAD + (u - 1)] : NEGF;
                    const float mx = fmaxf(up, left);
                    const float mn = fminf(up, left);
                    val = mx + log1pf(__expf(mn - mx));
                }
                if (t == t_last && u == u_last) {
                    out[b] = -(val + s_lpb[t * SPAD + u]);
                }
            }
            sh[cb][u] = val;
            myPrev = val;
        }
        __syncthreads();
    }
}

// ---------------------------------------------------------------------------
// Launch
// ---------------------------------------------------------------------------
extern "C" void kernel_launch(void* const* d_in, const int* in_sizes, int n_in,
                              void* d_out, int out_size)
{
    const float* logits         = (const float*)d_in[0];
    const int*   targets        = (const int*)d_in[1];
    const int*   logit_lengths  = (const int*)d_in[2];
    const int*   target_lengths = (const int*)d_in[3];
    float*       out            = (float*)d_out;

    const int nrows   = Bn * Tn * U1;          // 66560 rows, one warp each
    const int threads = 256;
    const int blocks  = (nrows * 32 + threads - 1) / threads;

    lse_gather_kernel<<<blocks, threads>>>(logits, targets);
    rnnt_dp_kernel<<<Bn, 128>>>(logit_lengths, target_lengths, out);
}